// round 1
// baseline (speedup 1.0000x reference)
#include <cuda_runtime.h>
#include <cuda_bf16.h>
#include <math.h>

#define H 1024
#define NEXP 16
#define TOPK 6
#define EPS 1e-10f
#define MAXT 8192
#define MAXPAIRS (MAXT * TOPK)

#define BM 128
#define BN 128
#define BK 16

// ---------------- device scratch (static, allowed) ----------------
__device__ int   g_counts[NEXP];
__device__ int   g_offsets[NEXP + 1];
__device__ int   g_cursor[NEXP];
__device__ int   g_idx[MAXPAIRS];      // top-k expert ids per token
__device__ float g_v[MAXPAIRS];        // combine weight per (token,k)
__device__ float g_sw[MAXT];           // sum of renormalized top-k probs
__device__ int   g_pair_token[MAXPAIRS];  // token id per sorted pair
__device__ float g_pairw[MAXPAIRS];       // weight per sorted pair
__device__ int   g_pos[MAXPAIRS];         // (token,k) -> sorted pair position
__device__ float g_Yp[(size_t)MAXPAIRS * H];  // expert outputs per pair (192MB)

// ---------------- small kernels ----------------
__global__ void reset_kernel() {
    int i = threadIdx.x;
    if (i < NEXP) g_counts[i] = 0;
}

__global__ void scan_kernel() {
    if (threadIdx.x == 0) {
        int off = 0;
        for (int e = 0; e < NEXP; ++e) {
            g_offsets[e] = off;
            g_cursor[e]  = off;
            off += g_counts[e];
        }
        g_offsets[NEXP] = off;
    }
}

// ---------------- router: warp per token ----------------
__global__ void router_kernel(const float* __restrict__ x,
                              const float* __restrict__ rw,
                              const float* __restrict__ rb, int T) {
    extern __shared__ float s_rw[];   // NEXP * H floats = 64KB
    __shared__ int s_cnt[NEXP];

    int tid = threadIdx.x;
    for (int i = tid; i < NEXP * H; i += blockDim.x) s_rw[i] = rw[i];
    if (tid < NEXP) s_cnt[tid] = 0;
    __syncthreads();

    int warp = tid >> 5, lane = tid & 31;
    int t = blockIdx.x * (blockDim.x >> 5) + warp;
    if (t < T) {
        const float* xr = x + (size_t)t * H;
        float acc[NEXP];
        #pragma unroll
        for (int e = 0; e < NEXP; ++e) acc[e] = 0.f;
        for (int i = lane; i < H; i += 32) {
            float xv = xr[i];
            #pragma unroll
            for (int e = 0; e < NEXP; ++e) acc[e] += xv * s_rw[e * H + i];
        }
        #pragma unroll
        for (int e = 0; e < NEXP; ++e) {
            #pragma unroll
            for (int o = 16; o > 0; o >>= 1)
                acc[e] += __shfl_xor_sync(0xffffffffu, acc[e], o);
        }
        float logit = (lane < NEXP) ? (acc[lane] + rb[lane]) : -INFINITY;

        // softmax across lanes 0..15
        float mx = logit;
        #pragma unroll
        for (int o = 16; o > 0; o >>= 1)
            mx = fmaxf(mx, __shfl_xor_sync(0xffffffffu, mx, o));
        float p = (lane < NEXP) ? expf(logit - mx) : 0.f;
        float sum = p;
        #pragma unroll
        for (int o = 16; o > 0; o >>= 1)
            sum += __shfl_xor_sync(0xffffffffu, sum, o);
        float prob = p / sum;

        // top-6 (distinct), tie -> lower index
        float cur = (lane < NEXP) ? prob : -1.f;
        float topv0, topv1, topv2, topv3, topv4, topv5;
        int   topi0, topi1, topi2, topi3, topi4, topi5;
        float s = 0.f;
        #pragma unroll
        for (int k = 0; k < TOPK; ++k) {
            float v = cur; int bi = lane;
            #pragma unroll
            for (int o = 16; o > 0; o >>= 1) {
                float ov = __shfl_xor_sync(0xffffffffu, v, o);
                int   oi = __shfl_xor_sync(0xffffffffu, bi, o);
                if (ov > v || (ov == v && oi < bi)) { v = ov; bi = oi; }
            }
            if (k == 0) { topv0 = v; topi0 = bi; }
            else if (k == 1) { topv1 = v; topi1 = bi; }
            else if (k == 2) { topv2 = v; topi2 = bi; }
            else if (k == 3) { topv3 = v; topi3 = bi; }
            else if (k == 4) { topv4 = v; topi4 = bi; }
            else             { topv5 = v; topi5 = bi; }
            s += v;
            if (lane == bi) cur = -1.f;
        }
        if (lane == 0) {
            float inv = 1.f / (s + EPS);
            float w0 = topv0 * inv, w1 = topv1 * inv, w2 = topv2 * inv;
            float w3 = topv3 * inv, w4 = topv4 * inv, w5 = topv5 * inv;
            float sw = w0 + w1 + w2 + w3 + w4 + w5;
            g_sw[t] = sw;
            float isw = 1.f / sw;
            int b = t * TOPK;
            g_idx[b + 0] = topi0; g_v[b + 0] = w0 * isw;
            g_idx[b + 1] = topi1; g_v[b + 1] = w1 * isw;
            g_idx[b + 2] = topi2; g_v[b + 2] = w2 * isw;
            g_idx[b + 3] = topi3; g_v[b + 3] = w3 * isw;
            g_idx[b + 4] = topi4; g_v[b + 4] = w4 * isw;
            g_idx[b + 5] = topi5; g_v[b + 5] = w5 * isw;
            atomicAdd(&s_cnt[topi0], 1); atomicAdd(&s_cnt[topi1], 1);
            atomicAdd(&s_cnt[topi2], 1); atomicAdd(&s_cnt[topi3], 1);
            atomicAdd(&s_cnt[topi4], 1); atomicAdd(&s_cnt[topi5], 1);
        }
    }
    __syncthreads();
    if (tid < NEXP && s_cnt[tid] > 0) atomicAdd(&g_counts[tid], s_cnt[tid]);
}

// ---------------- scatter pairs into per-expert segments ----------------
__global__ void scatter_kernel(int T) {
    int p = blockIdx.x * blockDim.x + threadIdx.x;
    if (p >= T * TOPK) return;
    int t = p / TOPK;
    int e = g_idx[p];
    int pos = atomicAdd(&g_cursor[e], 1);
    g_pair_token[pos] = t;
    g_pairw[pos] = g_v[p];
    g_pos[p] = pos;
}

// ---------------- grouped GEMM: Yp[pair] = w_pair * (X[tok] @ W_e) ----------------
__device__ __forceinline__ unsigned f2tf(float f) {
    unsigned u;
    asm("cvt.rna.tf32.f32 %0, %1;" : "=r"(u) : "f"(f));
    return u;
}

__device__ __forceinline__ void mma8(float* c, const unsigned* a, const unsigned* b) {
    asm volatile(
        "mma.sync.aligned.m16n8k8.row.col.f32.tf32.tf32.f32 "
        "{%0,%1,%2,%3}, {%4,%5,%6,%7}, {%8,%9}, {%0,%1,%2,%3};"
        : "+f"(c[0]), "+f"(c[1]), "+f"(c[2]), "+f"(c[3])
        : "r"(a[0]), "r"(a[1]), "r"(a[2]), "r"(a[3]), "r"(b[0]), "r"(b[1]));
}

__global__ void __launch_bounds__(256) gemm_kernel(const float* __restrict__ X,
                                                   const float* __restrict__ EW) {
    const int e = blockIdx.z;
    const int m_base = g_offsets[e] + blockIdx.y * BM;
    const int m_end  = g_offsets[e + 1];
    if (m_base >= m_end) return;

    __shared__ unsigned As[2][BM][BK + 4];
    __shared__ unsigned Bs[2][BK][BN + 8];
    __shared__ int   s_tok[BM];
    __shared__ float s_w[BM];

    const int tid = threadIdx.x;
    if (tid < BM) {
        int r = m_base + tid;
        s_tok[tid] = (r < m_end) ? g_pair_token[r] : 0;
        s_w[tid]   = (r < m_end) ? g_pairw[r] : 0.f;
    }
    __syncthreads();

    const float* wb = EW + (size_t)e * H * H + (size_t)blockIdx.x * BN;

    const int arow = tid >> 2;     // 0..63, +64 on 2nd iter
    const int aq   = tid & 3;      // float4 quad within BK=16
    const int brow = tid >> 5;     // 0..7,  +8 on 2nd iter
    const int bq   = tid & 31;     // float4 quad within BN=128

    float4 ra[2], rbv[2];

    #define LDG_A(k0)                                                        \
        { _Pragma("unroll")                                                  \
          for (int i = 0; i < 2; ++i) {                                      \
            int row = arow + i * 64;                                         \
            ra[i] = *(const float4*)(X + (size_t)s_tok[row] * H + (k0) + aq * 4); } }
    #define LDG_B(k0)                                                        \
        { _Pragma("unroll")                                                  \
          for (int i = 0; i < 2; ++i) {                                      \
            int kr = brow + i * 8;                                           \
            rbv[i] = *(const float4*)(wb + (size_t)((k0) + kr) * H + bq * 4); } }
    #define STS_AB(st)                                                       \
        { _Pragma("unroll")                                                  \
          for (int i = 0; i < 2; ++i) {                                      \
            int row = arow + i * 64;                                         \
            unsigned* d = &As[st][row][aq * 4];                              \
            d[0] = f2tf(ra[i].x); d[1] = f2tf(ra[i].y);                      \
            d[2] = f2tf(ra[i].z); d[3] = f2tf(ra[i].w); }                    \
          _Pragma("unroll")                                                  \
          for (int i = 0; i < 2; ++i) {                                      \
            int kr = brow + i * 8;                                           \
            unsigned* d = &Bs[st][kr][bq * 4];                               \
            d[0] = f2tf(rbv[i].x); d[1] = f2tf(rbv[i].y);                    \
            d[2] = f2tf(rbv[i].z); d[3] = f2tf(rbv[i].w); } }

    LDG_A(0); LDG_B(0);
    STS_AB(0);
    __syncthreads();

    float c[4][4][4];
    #pragma unroll
    for (int mi = 0; mi < 4; ++mi)
        #pragma unroll
        for (int ni = 0; ni < 4; ++ni)
            #pragma unroll
            for (int j = 0; j < 4; ++j) c[mi][ni][j] = 0.f;

    const int lane = tid & 31;
    const int grp = lane >> 2, tg = lane & 3;
    const int wid = tid >> 5;
    const int wm = (wid >> 2) * 64;   // warp m offset (2 rows of warps)
    const int wn = (wid & 3) * 32;    // warp n offset (4 cols of warps)

    const int NK = H / BK;  // 64
    for (int kt = 0; kt < NK; ++kt) {
        const int curb = kt & 1;
        if (kt + 1 < NK) { LDG_A((kt + 1) * BK); LDG_B((kt + 1) * BK); }

        #pragma unroll
        for (int kk = 0; kk < 2; ++kk) {
            const int k8 = kk * 8;
            unsigned a[4][4], b[4][2];
            #pragma unroll
            for (int mi = 0; mi < 4; ++mi) {
                int r = wm + mi * 16 + grp;
                a[mi][0] = As[curb][r][k8 + tg];
                a[mi][1] = As[curb][r + 8][k8 + tg];
                a[mi][2] = As[curb][r][k8 + tg + 4];
                a[mi][3] = As[curb][r + 8][k8 + tg + 4];
            }
            #pragma unroll
            for (int ni = 0; ni < 4; ++ni) {
                int cn = wn + ni * 8 + grp;
                b[ni][0] = Bs[curb][k8 + tg][cn];
                b[ni][1] = Bs[curb][k8 + tg + 4][cn];
            }
            #pragma unroll
            for (int mi = 0; mi < 4; ++mi)
                #pragma unroll
                for (int ni = 0; ni < 4; ++ni)
                    mma8(c[mi][ni], a[mi], b[ni]);
        }

        if (kt + 1 < NK) {
            STS_AB(curb ^ 1);
            __syncthreads();
        }
    }

    // epilogue: scale by pair weight, store float2s
    const int n0 = blockIdx.x * BN;
    #pragma unroll
    for (int mi = 0; mi < 4; ++mi) {
        int rl0 = wm + mi * 16 + grp;
        int rl1 = rl0 + 8;
        int gr0 = m_base + rl0;
        int gr1 = m_base + rl1;
        float w0 = s_w[rl0], w1 = s_w[rl1];
        #pragma unroll
        for (int ni = 0; ni < 4; ++ni) {
            int col = n0 + wn + ni * 8 + tg * 2;
            if (gr0 < m_end) {
                float2 v = make_float2(c[mi][ni][0] * w0, c[mi][ni][1] * w0);
                *(float2*)&g_Yp[(size_t)gr0 * H + col] = v;
            }
            if (gr1 < m_end) {
                float2 v = make_float2(c[mi][ni][2] * w1, c[mi][ni][3] * w1);
                *(float2*)&g_Yp[(size_t)gr1 * H + col] = v;
            }
        }
    }
    #undef LDG_A
    #undef LDG_B
    #undef STS_AB
}

// ---------------- combine: out[t] = EPS*sw + sum_k Yp[pos_k] ----------------
__global__ void combine_kernel(float* __restrict__ out, int T) {
    int t = blockIdx.x;
    int c4 = threadIdx.x;             // 256 threads * float4 = 1024 cols
    int b = t * TOPK;
    int p0 = g_pos[b + 0], p1 = g_pos[b + 1], p2 = g_pos[b + 2];
    int p3 = g_pos[b + 3], p4 = g_pos[b + 4], p5 = g_pos[b + 5];
    float bias = EPS * g_sw[t];
    int col = c4 * 4;

    float4 acc = make_float4(bias, bias, bias, bias);
    float4 y;
    y = *(const float4*)&g_Yp[(size_t)p0 * H + col]; acc.x += y.x; acc.y += y.y; acc.z += y.z; acc.w += y.w;
    y = *(const float4*)&g_Yp[(size_t)p1 * H + col]; acc.x += y.x; acc.y += y.y; acc.z += y.z; acc.w += y.w;
    y = *(const float4*)&g_Yp[(size_t)p2 * H + col]; acc.x += y.x; acc.y += y.y; acc.z += y.z; acc.w += y.w;
    y = *(const float4*)&g_Yp[(size_t)p3 * H + col]; acc.x += y.x; acc.y += y.y; acc.z += y.z; acc.w += y.w;
    y = *(const float4*)&g_Yp[(size_t)p4 * H + col]; acc.x += y.x; acc.y += y.y; acc.z += y.z; acc.w += y.w;
    y = *(const float4*)&g_Yp[(size_t)p5 * H + col]; acc.x += y.x; acc.y += y.y; acc.z += y.z; acc.w += y.w;

    *(float4*)&out[(size_t)t * H + col] = acc;
}

// ---------------- launch ----------------
extern "C" void kernel_launch(void* const* d_in, const int* in_sizes, int n_in,
                              void* d_out, int out_size) {
    const float* tokens = (const float*)d_in[0];
    const float* rw     = (const float*)d_in[1];
    const float* rb     = (const float*)d_in[2];
    const float* ew     = (const float*)d_in[3];
    float* out = (float*)d_out;

    int T = in_sizes[0] / H;   // 8192

    reset_kernel<<<1, 32>>>();

    cudaFuncSetAttribute(router_kernel,
                         cudaFuncAttributeMaxDynamicSharedMemorySize, NEXP * H * 4);
    int warps_per_blk = 8;
    int rblocks = (T + warps_per_blk - 1) / warps_per_blk;
    router_kernel<<<rblocks, warps_per_blk * 32, NEXP * H * 4>>>(tokens, rw, rb, T);

    scan_kernel<<<1, 32>>>();

    scatter_kernel<<<(T * TOPK + 255) / 256, 256>>>(T);

    dim3 ggrid(H / BN, (T + BM - 1) / BM, NEXP);
    gemm_kernel<<<ggrid, 256>>>(tokens, ew);

    combine_kernel<<<T, 256>>>(out, T);
}

// round 4
// speedup vs baseline: 1.1004x; 1.1004x over previous
#include <cuda_runtime.h>
#include <math.h>
#include <cstdint>

#define H 1024
#define NEXP 16
#define TOPK 6
#define EPS 1e-10f
#define MAXT 8192
#define MAXPAIRS (MAXT * TOPK)

// GEMM tiling (Ampere-path tf32 mma.sync; tcgen05 unavailable: PTX target is compute_103)
#define BM 128
#define BN 256
#define BKK 32
#define NKT (H / BKK)          // 32
#define STG 3
#define AST 36                 // A smem row stride in words
#define BSTRIDE 264            // B smem row stride in words
#define A_BYTES (BM * AST * 4)          // 18432
#define B_BYTES (BKK * BSTRIDE * 4)     // 33792
#define STAGE_BYTES (A_BYTES + B_BYTES) // 52224
#define SM_TOK (STG * STAGE_BYTES)      // 156672
#define SM_W   (SM_TOK + 512)
#define SM_TOTAL (SM_W + 512)           // 157696

// ---------------- device scratch ----------------
__device__ int   g_counts[NEXP];
__device__ int   g_offsets[NEXP + 1];
__device__ int   g_cursor[NEXP];
__device__ int   g_idx[MAXPAIRS];
__device__ float g_v[MAXPAIRS];
__device__ float g_sw[MAXT];
__device__ int   g_pair_token[MAXPAIRS];
__device__ float g_pairw[MAXPAIRS];
__device__ int   g_pos[MAXPAIRS];
__device__ float g_Yp[(size_t)MAXPAIRS * H];     // 192MB
__device__ float g_Wt[(size_t)NEXP * H * H];     // 64MB  tf32-converted W
__device__ float g_Xt[(size_t)MAXT * H];         // 32MB  tf32-converted tokens

// ---------------- helpers ----------------
__device__ __forceinline__ unsigned f2tf(float f) {
    unsigned u;
    asm("cvt.rna.tf32.f32 %0, %1;" : "=r"(u) : "f"(f));
    return u;
}
__device__ __forceinline__ uint32_t s2u(const void* p) {
    uint32_t a;
    asm("{ .reg .u64 t; cvta.to.shared.u64 t, %1; cvt.u32.u64 %0, t; }"
        : "=r"(a) : "l"(p));
    return a;
}
__device__ __forceinline__ void cpa16(uint32_t dst, const void* src) {
    asm volatile("cp.async.cg.shared.global [%0], [%1], 16;" :: "r"(dst), "l"(src));
}
__device__ __forceinline__ void cpa_commit() {
    asm volatile("cp.async.commit_group;" ::: "memory");
}
__device__ __forceinline__ void cpa_wait1() {
    asm volatile("cp.async.wait_group 1;" ::: "memory");
}
__device__ __forceinline__ void mma8(float* c, const unsigned* a, const unsigned* b) {
    asm volatile(
        "mma.sync.aligned.m16n8k8.row.col.f32.tf32.tf32.f32 "
        "{%0,%1,%2,%3}, {%4,%5,%6,%7}, {%8,%9}, {%0,%1,%2,%3};"
        : "+f"(c[0]), "+f"(c[1]), "+f"(c[2]), "+f"(c[3])
        : "r"(a[0]), "r"(a[1]), "r"(a[2]), "r"(a[3]), "r"(b[0]), "r"(b[1]));
}

// ---------------- small kernels ----------------
__global__ void reset_kernel() {
    int i = threadIdx.x;
    if (i < NEXP) g_counts[i] = 0;
}

__global__ void scan_kernel() {
    if (threadIdx.x == 0) {
        int off = 0;
        for (int e = 0; e < NEXP; ++e) {
            g_offsets[e] = off;
            g_cursor[e]  = off;
            off += g_counts[e];
        }
        g_offsets[NEXP] = off;
    }
}

// pre-convert fp32 -> tf32 bit patterns into device globals.
// NOTE: destination is a __device__ global referenced from DEVICE code only —
// passing g_Xt/g_Wt as host-side kernel args was the round-3 bug (host code
// cannot take the address of a __device__ symbol).
__global__ void cvt_x_kernel(const float* __restrict__ src, int n4) {
    int i = blockIdx.x * blockDim.x + threadIdx.x;
    if (i >= n4) return;
    float4 v = ((const float4*)src)[i];
    uint4 u;
    u.x = f2tf(v.x); u.y = f2tf(v.y); u.z = f2tf(v.z); u.w = f2tf(v.w);
    ((uint4*)g_Xt)[i] = u;
}
__global__ void cvt_w_kernel(const float* __restrict__ src, int n4) {
    int i = blockIdx.x * blockDim.x + threadIdx.x;
    if (i >= n4) return;
    float4 v = ((const float4*)src)[i];
    uint4 u;
    u.x = f2tf(v.x); u.y = f2tf(v.y); u.z = f2tf(v.z); u.w = f2tf(v.w);
    ((uint4*)g_Wt)[i] = u;
}

// ---------------- router: warp per token ----------------
__global__ void router_kernel(const float* __restrict__ x,
                              const float* __restrict__ rw,
                              const float* __restrict__ rb, int T) {
    extern __shared__ float s_rw[];
    __shared__ int s_cnt[NEXP];

    int tid = threadIdx.x;
    for (int i = tid; i < NEXP * H; i += blockDim.x) s_rw[i] = rw[i];
    if (tid < NEXP) s_cnt[tid] = 0;
    __syncthreads();

    int warp = tid >> 5, lane = tid & 31;
    int t = blockIdx.x * (blockDim.x >> 5) + warp;
    if (t < T) {
        const float* xr = x + (size_t)t * H;
        float acc[NEXP];
        #pragma unroll
        for (int e = 0; e < NEXP; ++e) acc[e] = 0.f;
        for (int i = lane; i < H; i += 32) {
            float xv = xr[i];
            #pragma unroll
            for (int e = 0; e < NEXP; ++e) acc[e] += xv * s_rw[e * H + i];
        }
        #pragma unroll
        for (int e = 0; e < NEXP; ++e) {
            #pragma unroll
            for (int o = 16; o > 0; o >>= 1)
                acc[e] += __shfl_xor_sync(0xffffffffu, acc[e], o);
        }
        float logit = (lane < NEXP) ? (acc[lane] + rb[lane]) : -INFINITY;

        float mx = logit;
        #pragma unroll
        for (int o = 16; o > 0; o >>= 1)
            mx = fmaxf(mx, __shfl_xor_sync(0xffffffffu, mx, o));
        float p = (lane < NEXP) ? expf(logit - mx) : 0.f;
        float sum = p;
        #pragma unroll
        for (int o = 16; o > 0; o >>= 1)
            sum += __shfl_xor_sync(0xffffffffu, sum, o);
        float prob = p / sum;

        float cur = (lane < NEXP) ? prob : -1.f;
        float tv[TOPK]; int ti[TOPK];
        float s = 0.f;
        #pragma unroll
        for (int k = 0; k < TOPK; ++k) {
            float v = cur; int bi = lane;
            #pragma unroll
            for (int o = 16; o > 0; o >>= 1) {
                float ov = __shfl_xor_sync(0xffffffffu, v, o);
                int   oi = __shfl_xor_sync(0xffffffffu, bi, o);
                if (ov > v || (ov == v && oi < bi)) { v = ov; bi = oi; }
            }
            tv[k] = v; ti[k] = bi;
            s += v;
            if (lane == bi) cur = -1.f;
        }
        if (lane == 0) {
            float inv = 1.f / (s + EPS);
            float w[TOPK], sw = 0.f;
            #pragma unroll
            for (int k = 0; k < TOPK; ++k) { w[k] = tv[k] * inv; sw += w[k]; }
            g_sw[t] = sw;
            float isw = 1.f / sw;
            int b = t * TOPK;
            #pragma unroll
            for (int k = 0; k < TOPK; ++k) {
                g_idx[b + k] = ti[k];
                g_v[b + k] = w[k] * isw;
                atomicAdd(&s_cnt[ti[k]], 1);
            }
        }
    }
    __syncthreads();
    if (tid < NEXP && s_cnt[tid] > 0) atomicAdd(&g_counts[tid], s_cnt[tid]);
}

// ---------------- scatter pairs into per-expert segments ----------------
__global__ void scatter_kernel(int T) {
    int p = blockIdx.x * blockDim.x + threadIdx.x;
    if (p >= T * TOPK) return;
    int t = p / TOPK;
    int e = g_idx[p];
    int pos = atomicAdd(&g_cursor[e], 1);
    g_pair_token[pos] = t;
    g_pairw[pos] = g_v[p];
    g_pos[p] = pos;
}

// ---------------- grouped GEMM: 128x256x32 tiles, cp.async 3-stage, tf32 mma ----------------
__global__ void __launch_bounds__(256, 1) gemm_kernel() {
    extern __shared__ char smem[];
    const int e = blockIdx.z;
    const int m_base = g_offsets[e] + blockIdx.y * BM;
    const int m_end  = g_offsets[e + 1];
    if (m_base >= m_end) return;
    const int n0 = blockIdx.x * BN;

    const uint32_t sb = s2u(smem);
    const int tid = threadIdx.x;
    int*   s_tok = (int*)(smem + SM_TOK);
    float* s_w   = (float*)(smem + SM_W);

    if (tid < BM) {
        int r = m_base + tid;
        s_tok[tid] = (r < m_end) ? g_pair_token[r] : 0;
        s_w[tid]   = (r < m_end) ? g_pairw[r] : 0.f;
    }
    __syncthreads();

    const float* wb = g_Wt + (size_t)e * H * H + n0;

    auto issue = [&](int s, int kt) {
        const int k0 = kt * BKK;
        uint32_t ab = sb + s * STAGE_BYTES;
        #pragma unroll
        for (int p = 0; p < 4; ++p) {
            int idx = tid + p * 256;
            int row = idx >> 3, i = idx & 7;
            cpa16(ab + (row * AST + i * 4) * 4,
                  g_Xt + (size_t)s_tok[row] * H + k0 + i * 4);
        }
        uint32_t bb = ab + A_BYTES;
        #pragma unroll
        for (int p = 0; p < 8; ++p) {
            int idx = tid + p * 256;
            int kr = idx >> 6, i = idx & 63;
            cpa16(bb + (kr * BSTRIDE + i * 4) * 4,
                  wb + (size_t)(k0 + kr) * H + i * 4);
        }
    };

    issue(0, 0); cpa_commit();
    issue(1, 1); cpa_commit();

    float c[4][8][4];
    #pragma unroll
    for (int mi = 0; mi < 4; ++mi)
        #pragma unroll
        for (int ni = 0; ni < 8; ++ni)
            #pragma unroll
            for (int j = 0; j < 4; ++j) c[mi][ni][j] = 0.f;

    const int lane = tid & 31;
    const int grp = lane >> 2, tg = lane & 3;
    const int wid = tid >> 5;
    const int wm = (wid >> 2) * 64;
    const int wn = (wid & 3) * 64;

    for (int kt = 0; kt < NKT; ++kt) {
        cpa_wait1();
        __syncthreads();
        if (kt + 2 < NKT) issue((kt + 2) % STG, kt + 2);
        cpa_commit();

        const unsigned* As = (const unsigned*)(smem + (kt % STG) * STAGE_BYTES);
        const unsigned* Bs = As + BM * AST;

        #pragma unroll
        for (int kk = 0; kk < 4; ++kk) {
            const int k8 = kk * 8;
            unsigned a[4][4], b[8][2];
            #pragma unroll
            for (int mi = 0; mi < 4; ++mi) {
                int r = wm + mi * 16 + grp;
                a[mi][0] = As[r * AST + k8 + tg];
                a[mi][1] = As[(r + 8) * AST + k8 + tg];
                a[mi][2] = As[r * AST + k8 + tg + 4];
                a[mi][3] = As[(r + 8) * AST + k8 + tg + 4];
            }
            #pragma unroll
            for (int ni = 0; ni < 8; ++ni) {
                int cn = wn + ni * 8 + grp;
                b[ni][0] = Bs[(k8 + tg) * BSTRIDE + cn];
                b[ni][1] = Bs[(k8 + tg + 4) * BSTRIDE + cn];
            }
            #pragma unroll
            for (int mi = 0; mi < 4; ++mi)
                #pragma unroll
                for (int ni = 0; ni < 8; ++ni)
                    mma8(c[mi][ni], a[mi], b[ni]);
        }
    }

    // epilogue: scale by pair weight, store float2
    #pragma unroll
    for (int mi = 0; mi < 4; ++mi) {
        int rl0 = wm + mi * 16 + grp;
        int rl1 = rl0 + 8;
        int gr0 = m_base + rl0;
        int gr1 = m_base + rl1;
        float w0 = s_w[rl0], w1 = s_w[rl1];
        #pragma unroll
        for (int ni = 0; ni < 8; ++ni) {
            int col = n0 + wn + ni * 8 + tg * 2;
            if (gr0 < m_end) {
                float2 v = make_float2(c[mi][ni][0] * w0, c[mi][ni][1] * w0);
                *(float2*)&g_Yp[(size_t)gr0 * H + col] = v;
            }
            if (gr1 < m_end) {
                float2 v = make_float2(c[mi][ni][2] * w1, c[mi][ni][3] * w1);
                *(float2*)&g_Yp[(size_t)gr1 * H + col] = v;
            }
        }
    }
}

// ---------------- combine: out[t] = EPS*sw + sum_k Yp[pos_k] ----------------
__global__ void combine_kernel(float* __restrict__ out, int T) {
    int t = blockIdx.x;
    int c4 = threadIdx.x;
    int b = t * TOPK;
    int p0 = g_pos[b + 0], p1 = g_pos[b + 1], p2 = g_pos[b + 2];
    int p3 = g_pos[b + 3], p4 = g_pos[b + 4], p5 = g_pos[b + 5];
    float bias = EPS * g_sw[t];
    int col = c4 * 4;

    float4 acc = make_float4(bias, bias, bias, bias);
    float4 y;
    y = *(const float4*)&g_Yp[(size_t)p0 * H + col]; acc.x += y.x; acc.y += y.y; acc.z += y.z; acc.w += y.w;
    y = *(const float4*)&g_Yp[(size_t)p1 * H + col]; acc.x += y.x; acc.y += y.y; acc.z += y.z; acc.w += y.w;
    y = *(const float4*)&g_Yp[(size_t)p2 * H + col]; acc.x += y.x; acc.y += y.y; acc.z += y.z; acc.w += y.w;
    y = *(const float4*)&g_Yp[(size_t)p3 * H + col]; acc.x += y.x; acc.y += y.y; acc.z += y.z; acc.w += y.w;
    y = *(const float4*)&g_Yp[(size_t)p4 * H + col]; acc.x += y.x; acc.y += y.y; acc.z += y.z; acc.w += y.w;
    y = *(const float4*)&g_Yp[(size_t)p5 * H + col]; acc.x += y.x; acc.y += y.y; acc.z += y.z; acc.w += y.w;

    *(float4*)&out[(size_t)t * H + col] = acc;
}

// ---------------- launch ----------------
extern "C" void kernel_launch(void* const* d_in, const int* in_sizes, int n_in,
                              void* d_out, int out_size) {
    const float* tokens = (const float*)d_in[0];
    const float* rw     = (const float*)d_in[1];
    const float* rb     = (const float*)d_in[2];
    const float* ew     = (const float*)d_in[3];
    float* out = (float*)d_out;

    int T = in_sizes[0] / H;   // 8192

    reset_kernel<<<1, 32>>>();

    cvt_x_kernel<<<(T * H / 4 + 255) / 256, 256>>>(tokens, T * H / 4);
    cvt_w_kernel<<<(NEXP * H * H / 4 + 255) / 256, 256>>>(ew, NEXP * H * H / 4);

    cudaFuncSetAttribute(router_kernel,
                         cudaFuncAttributeMaxDynamicSharedMemorySize, NEXP * H * 4);
    int warps_per_blk = 8;
    int rblocks = (T + warps_per_blk - 1) / warps_per_blk;
    router_kernel<<<rblocks, warps_per_blk * 32, NEXP * H * 4>>>(tokens, rw, rb, T);

    scan_kernel<<<1, 32>>>();

    scatter_kernel<<<(T * TOPK + 255) / 256, 256>>>(T);

    cudaFuncSetAttribute(gemm_kernel,
                         cudaFuncAttributeMaxDynamicSharedMemorySize, SM_TOTAL);
    dim3 ggrid(H / BN, (T * TOPK + BM - 1) / BM, NEXP);  // (4, 384, 16); empty tiles exit
    gemm_kernel<<<ggrid, 256, SM_TOTAL>>>();

    combine_kernel<<<T, 256>>>(out, T);
}

// round 5
// speedup vs baseline: 1.1254x; 1.0227x over previous
#include <cuda_runtime.h>
#include <math.h>
#include <cstdint>

#define H 1024
#define NEXP 16
#define TOPK 6
#define EPS 1e-10f
#define MAXT 8192
#define MAXPAIRS (MAXT * TOPK)

// GEMM tiling (Ampere-path tf32 mma.sync; tcgen05 unavailable on compute_103 target)
#define BM 128
#define BN 256
#define BKK 32
#define NKT (H / BKK)          // 32
#define STG 4
#define AST 36                 // A smem row stride in words
#define BSTRIDE 264            // B smem row stride in words
#define A_BYTES (BM * AST * 4)          // 18432
#define B_BYTES (BKK * BSTRIDE * 4)     // 33792
#define STAGE_BYTES (A_BYTES + B_BYTES) // 52224
#define SM_TOK (STG * STAGE_BYTES)      // 208896
#define SM_W   (SM_TOK + 512)
#define SM_TOTAL (SM_W + 512)           // 209920 (< 227KB max dynamic)

#define NTILES_MAX 400   // ceil(49152/128) + 15 partial = 399

// ---------------- device scratch ----------------
__device__ int   g_counts[NEXP];
__device__ int   g_offsets[NEXP + 1];
__device__ int   g_cursor[NEXP];
__device__ int   g_ntiles;
__device__ int   g_tile_e[NTILES_MAX];
__device__ int   g_tile_m[NTILES_MAX];
__device__ int   g_idx[MAXPAIRS];
__device__ float g_v[MAXPAIRS];
__device__ float g_sw[MAXT];
__device__ int   g_pair_token[MAXPAIRS];
__device__ float g_pairw[MAXPAIRS];
__device__ int   g_pos[MAXPAIRS];
__device__ float g_Yp[(size_t)MAXPAIRS * H];     // 192MB
__device__ float g_Wt[(size_t)NEXP * H * H];     // 64MB  tf32-converted W
__device__ float g_Xt[(size_t)MAXT * H];         // 32MB  tf32-converted tokens

// ---------------- helpers ----------------
__device__ __forceinline__ unsigned f2tf(float f) {
    unsigned u;
    asm("cvt.rna.tf32.f32 %0, %1;" : "=r"(u) : "f"(f));
    return u;
}
__device__ __forceinline__ uint32_t s2u(const void* p) {
    uint32_t a;
    asm("{ .reg .u64 t; cvta.to.shared.u64 t, %1; cvt.u32.u64 %0, t; }"
        : "=r"(a) : "l"(p));
    return a;
}
__device__ __forceinline__ void cpa16(uint32_t dst, const void* src) {
    asm volatile("cp.async.cg.shared.global [%0], [%1], 16;" :: "r"(dst), "l"(src));
}
__device__ __forceinline__ void cpa_commit() {
    asm volatile("cp.async.commit_group;" ::: "memory");
}
__device__ __forceinline__ void cpa_wait2() {
    asm volatile("cp.async.wait_group 2;" ::: "memory");
}
__device__ __forceinline__ void mma8(float* c, const unsigned* a, const unsigned* b) {
    asm volatile(
        "mma.sync.aligned.m16n8k8.row.col.f32.tf32.tf32.f32 "
        "{%0,%1,%2,%3}, {%4,%5,%6,%7}, {%8,%9}, {%0,%1,%2,%3};"
        : "+f"(c[0]), "+f"(c[1]), "+f"(c[2]), "+f"(c[3])
        : "r"(a[0]), "r"(a[1]), "r"(a[2]), "r"(a[3]), "r"(b[0]), "r"(b[1]));
}

// ---------------- small kernels ----------------
__global__ void reset_kernel() {
    int i = threadIdx.x;
    if (i < NEXP) g_counts[i] = 0;
}

// exclusive scan + exact M-tile table (kills the 23k empty-CTA launches)
__global__ void scan_kernel() {
    if (threadIdx.x == 0) {
        int off = 0, tiles = 0;
        for (int e = 0; e < NEXP; ++e) {
            g_offsets[e] = off;
            g_cursor[e]  = off;
            int cnt = g_counts[e];
            for (int m = 0; m < cnt; m += BM) {
                g_tile_e[tiles] = e;
                g_tile_m[tiles] = off + m;
                ++tiles;
            }
            off += cnt;
        }
        g_offsets[NEXP] = off;
        g_ntiles = tiles;
    }
}

// pre-convert fp32 -> tf32 bit patterns into device globals (device-side refs only)
__global__ void cvt_x_kernel(const float* __restrict__ src, int n4) {
    int i = blockIdx.x * blockDim.x + threadIdx.x;
    if (i >= n4) return;
    float4 v = ((const float4*)src)[i];
    uint4 u;
    u.x = f2tf(v.x); u.y = f2tf(v.y); u.z = f2tf(v.z); u.w = f2tf(v.w);
    ((uint4*)g_Xt)[i] = u;
}
__global__ void cvt_w_kernel(const float* __restrict__ src, int n4) {
    int i = blockIdx.x * blockDim.x + threadIdx.x;
    if (i >= n4) return;
    float4 v = ((const float4*)src)[i];
    uint4 u;
    u.x = f2tf(v.x); u.y = f2tf(v.y); u.z = f2tf(v.z); u.w = f2tf(v.w);
    ((uint4*)g_Wt)[i] = u;
}

// ---------------- router: warp per token ----------------
__global__ void router_kernel(const float* __restrict__ x,
                              const float* __restrict__ rw,
                              const float* __restrict__ rb, int T) {
    extern __shared__ float s_rw[];
    __shared__ int s_cnt[NEXP];

    int tid = threadIdx.x;
    for (int i = tid; i < NEXP * H; i += blockDim.x) s_rw[i] = rw[i];
    if (tid < NEXP) s_cnt[tid] = 0;
    __syncthreads();

    int warp = tid >> 5, lane = tid & 31;
    int t = blockIdx.x * (blockDim.x >> 5) + warp;
    if (t < T) {
        const float* xr = x + (size_t)t * H;
        float acc[NEXP];
        #pragma unroll
        for (int e = 0; e < NEXP; ++e) acc[e] = 0.f;
        for (int i = lane; i < H; i += 32) {
            float xv = xr[i];
            #pragma unroll
            for (int e = 0; e < NEXP; ++e) acc[e] += xv * s_rw[e * H + i];
        }
        #pragma unroll
        for (int e = 0; e < NEXP; ++e) {
            #pragma unroll
            for (int o = 16; o > 0; o >>= 1)
                acc[e] += __shfl_xor_sync(0xffffffffu, acc[e], o);
        }
        float logit = (lane < NEXP) ? (acc[lane] + rb[lane]) : -INFINITY;

        float mx = logit;
        #pragma unroll
        for (int o = 16; o > 0; o >>= 1)
            mx = fmaxf(mx, __shfl_xor_sync(0xffffffffu, mx, o));
        float p = (lane < NEXP) ? expf(logit - mx) : 0.f;
        float sum = p;
        #pragma unroll
        for (int o = 16; o > 0; o >>= 1)
            sum += __shfl_xor_sync(0xffffffffu, sum, o);
        float prob = p / sum;

        float cur = (lane < NEXP) ? prob : -1.f;
        float tv[TOPK]; int ti[TOPK];
        float s = 0.f;
        #pragma unroll
        for (int k = 0; k < TOPK; ++k) {
            float v = cur; int bi = lane;
            #pragma unroll
            for (int o = 16; o > 0; o >>= 1) {
                float ov = __shfl_xor_sync(0xffffffffu, v, o);
                int   oi = __shfl_xor_sync(0xffffffffu, bi, o);
                if (ov > v || (ov == v && oi < bi)) { v = ov; bi = oi; }
            }
            tv[k] = v; ti[k] = bi;
            s += v;
            if (lane == bi) cur = -1.f;
        }
        if (lane == 0) {
            float inv = 1.f / (s + EPS);
            float w[TOPK], sw = 0.f;
            #pragma unroll
            for (int k = 0; k < TOPK; ++k) { w[k] = tv[k] * inv; sw += w[k]; }
            g_sw[t] = sw;
            float isw = 1.f / sw;
            int b = t * TOPK;
            #pragma unroll
            for (int k = 0; k < TOPK; ++k) {
                g_idx[b + k] = ti[k];
                g_v[b + k] = w[k] * isw;
                atomicAdd(&s_cnt[ti[k]], 1);
            }
        }
    }
    __syncthreads();
    if (tid < NEXP && s_cnt[tid] > 0) atomicAdd(&g_counts[tid], s_cnt[tid]);
}

// ---------------- scatter pairs into per-expert segments ----------------
__global__ void scatter_kernel(int T) {
    int p = blockIdx.x * blockDim.x + threadIdx.x;
    if (p >= T * TOPK) return;
    int t = p / TOPK;
    int e = g_idx[p];
    int pos = atomicAdd(&g_cursor[e], 1);
    g_pair_token[pos] = t;
    g_pairw[pos] = g_v[p];
    g_pos[p] = pos;
}

// ---------------- grouped GEMM: 128x256x32 tiles, cp.async 4-stage, tf32 mma ----------------
__global__ void __launch_bounds__(256, 1) gemm_kernel() {
    extern __shared__ char smem[];
    const int tile = blockIdx.y;
    if (tile >= g_ntiles) return;
    const int e      = g_tile_e[tile];
    const int m_base = g_tile_m[tile];
    const int m_end  = g_offsets[e + 1];
    const int n0 = blockIdx.x * BN;

    const uint32_t sb = s2u(smem);
    const int tid = threadIdx.x;
    int*   s_tok = (int*)(smem + SM_TOK);
    float* s_w   = (float*)(smem + SM_W);

    if (tid < BM) {
        int r = m_base + tid;
        s_tok[tid] = (r < m_end) ? g_pair_token[r] : 0;
        s_w[tid]   = (r < m_end) ? g_pairw[r] : 0.f;
    }
    __syncthreads();

    const float* wb = g_Wt + (size_t)e * H * H + n0;

    auto issue = [&](int s, int kt) {
        const int k0 = kt * BKK;
        uint32_t ab = sb + s * STAGE_BYTES;
        #pragma unroll
        for (int p = 0; p < 4; ++p) {
            int idx = tid + p * 256;
            int row = idx >> 3, i = idx & 7;
            cpa16(ab + (row * AST + i * 4) * 4,
                  g_Xt + (size_t)s_tok[row] * H + k0 + i * 4);
        }
        uint32_t bb = ab + A_BYTES;
        #pragma unroll
        for (int p = 0; p < 8; ++p) {
            int idx = tid + p * 256;
            int kr = idx >> 6, i = idx & 63;
            cpa16(bb + (kr * BSTRIDE + i * 4) * 4,
                  wb + (size_t)(k0 + kr) * H + i * 4);
        }
    };

    issue(0, 0); cpa_commit();
    issue(1, 1); cpa_commit();
    issue(2, 2); cpa_commit();

    float c[4][8][4];
    #pragma unroll
    for (int mi = 0; mi < 4; ++mi)
        #pragma unroll
        for (int ni = 0; ni < 8; ++ni)
            #pragma unroll
            for (int j = 0; j < 4; ++j) c[mi][ni][j] = 0.f;

    const int lane = tid & 31;
    const int grp = lane >> 2, tg = lane & 3;
    const int wid = tid >> 5;
    const int wm = (wid >> 2) * 64;
    const int wn = (wid & 3) * 64;

    for (int kt = 0; kt < NKT; ++kt) {
        cpa_wait2();
        __syncthreads();
        if (kt + 3 < NKT) issue((kt + 3) % STG, kt + 3);
        cpa_commit();   // commit every iteration keeps wait_group(2) sound at tail

        const unsigned* As = (const unsigned*)(smem + (kt % STG) * STAGE_BYTES);
        const unsigned* Bs = As + BM * AST;

        #pragma unroll
        for (int kk = 0; kk < 4; ++kk) {
            const int k8 = kk * 8;
            unsigned a[4][4], b[8][2];
            #pragma unroll
            for (int mi = 0; mi < 4; ++mi) {
                int r = wm + mi * 16 + grp;
                a[mi][0] = As[r * AST + k8 + tg];
                a[mi][1] = As[(r + 8) * AST + k8 + tg];
                a[mi][2] = As[r * AST + k8 + tg + 4];
                a[mi][3] = As[(r + 8) * AST + k8 + tg + 4];
            }
            #pragma unroll
            for (int ni = 0; ni < 8; ++ni) {
                int cn = wn + ni * 8 + grp;
                b[ni][0] = Bs[(k8 + tg) * BSTRIDE + cn];
                b[ni][1] = Bs[(k8 + tg + 4) * BSTRIDE + cn];
            }
            #pragma unroll
            for (int mi = 0; mi < 4; ++mi)
                #pragma unroll
                for (int ni = 0; ni < 8; ++ni)
                    mma8(c[mi][ni], a[mi], b[ni]);
        }
    }

    // epilogue: scale by pair weight, store float2
    #pragma unroll
    for (int mi = 0; mi < 4; ++mi) {
        int rl0 = wm + mi * 16 + grp;
        int rl1 = rl0 + 8;
        int gr0 = m_base + rl0;
        int gr1 = m_base + rl1;
        float w0 = s_w[rl0], w1 = s_w[rl1];
        #pragma unroll
        for (int ni = 0; ni < 8; ++ni) {
            int col = n0 + wn + ni * 8 + tg * 2;
            if (gr0 < m_end) {
                float2 v = make_float2(c[mi][ni][0] * w0, c[mi][ni][1] * w0);
                *(float2*)&g_Yp[(size_t)gr0 * H + col] = v;
            }
            if (gr1 < m_end) {
                float2 v = make_float2(c[mi][ni][2] * w1, c[mi][ni][3] * w1);
                *(float2*)&g_Yp[(size_t)gr1 * H + col] = v;
            }
        }
    }
}

// ---------------- combine: out[t] = EPS*sw + sum_k Yp[pos_k] ----------------
__global__ void combine_kernel(float* __restrict__ out, int T) {
    int t = blockIdx.x;
    int c4 = threadIdx.x;
    int b = t * TOPK;
    int p0 = g_pos[b + 0], p1 = g_pos[b + 1], p2 = g_pos[b + 2];
    int p3 = g_pos[b + 3], p4 = g_pos[b + 4], p5 = g_pos[b + 5];
    float bias = EPS * g_sw[t];
    int col = c4 * 4;

    float4 acc = make_float4(bias, bias, bias, bias);
    float4 y;
    y = *(const float4*)&g_Yp[(size_t)p0 * H + col]; acc.x += y.x; acc.y += y.y; acc.z += y.z; acc.w += y.w;
    y = *(const float4*)&g_Yp[(size_t)p1 * H + col]; acc.x += y.x; acc.y += y.y; acc.z += y.z; acc.w += y.w;
    y = *(const float4*)&g_Yp[(size_t)p2 * H + col]; acc.x += y.x; acc.y += y.y; acc.z += y.z; acc.w += y.w;
    y = *(const float4*)&g_Yp[(size_t)p3 * H + col]; acc.x += y.x; acc.y += y.y; acc.z += y.z; acc.w += y.w;
    y = *(const float4*)&g_Yp[(size_t)p4 * H + col]; acc.x += y.x; acc.y += y.y; acc.z += y.z; acc.w += y.w;
    y = *(const float4*)&g_Yp[(size_t)p5 * H + col]; acc.x += y.x; acc.y += y.y; acc.z += y.z; acc.w += y.w;

    *(float4*)&out[(size_t)t * H + col] = acc;
}

// ---------------- launch ----------------
extern "C" void kernel_launch(void* const* d_in, const int* in_sizes, int n_in,
                              void* d_out, int out_size) {
    const float* tokens = (const float*)d_in[0];
    const float* rw     = (const float*)d_in[1];
    const float* rb     = (const float*)d_in[2];
    const float* ew     = (const float*)d_in[3];
    float* out = (float*)d_out;

    int T = in_sizes[0] / H;   // 8192

    reset_kernel<<<1, 32>>>();

    cvt_x_kernel<<<(T * H / 4 + 255) / 256, 256>>>(tokens, T * H / 4);
    cvt_w_kernel<<<(NEXP * H * H / 4 + 255) / 256, 256>>>(ew, NEXP * H * H / 4);

    cudaFuncSetAttribute(router_kernel,
                         cudaFuncAttributeMaxDynamicSharedMemorySize, NEXP * H * 4);
    int warps_per_blk = 8;
    int rblocks = (T + warps_per_blk - 1) / warps_per_blk;
    router_kernel<<<rblocks, warps_per_blk * 32, NEXP * H * 4>>>(tokens, rw, rb, T);

    scan_kernel<<<1, 32>>>();

    scatter_kernel<<<(T * TOPK + 255) / 256, 256>>>(T);

    cudaFuncSetAttribute(gemm_kernel,
                         cudaFuncAttributeMaxDynamicSharedMemorySize, SM_TOTAL);
    dim3 ggrid(H / BN, NTILES_MAX, 1);   // exact tile table; <=~60 idle CTAs
    gemm_kernel<<<ggrid, 256, SM_TOTAL>>>();

    combine_kernel<<<T, 256>>>(out, T);
}

// round 6
// speedup vs baseline: 1.1439x; 1.0164x over previous
#include <cuda_runtime.h>
#include <math.h>
#include <cstdint>

#define H 1024
#define NEXP 16
#define TOPK 6
#define EPS 1e-10f
#define MAXT 8192
#define SEG 8192              // fixed per-expert segment capacity

// GEMM tiling (Ampere-path tf32 mma.sync; tcgen05 unavailable on compute_103 target)
#define BM 128
#define BN 256
#define BKK 32
#define NKT (H / BKK)          // 32
#define STG 4
#define AST 36                 // A smem row stride in words
#define BSTRIDE 264            // B smem row stride in words
#define A_BYTES (BM * AST * 4)          // 18432
#define B_BYTES (BKK * BSTRIDE * 4)     // 33792
#define STAGE_BYTES (A_BYTES + B_BYTES) // 52224
#define SM_TOK (STG * STAGE_BYTES)      // 208896
#define SM_W   (SM_TOK + 512)
#define SM_TOTAL (SM_W + 512)           // 209920

// ---------------- device scratch ----------------
__device__ int   g_cursor[NEXP];                  // per-expert pair count (atomic)
__device__ float g_sw[MAXT];
__device__ int   g_pair_token[NEXP * SEG];
__device__ float g_pairw[NEXP * SEG];
__device__ int   g_pos[MAXT * TOPK];              // (token,k) -> global pair row
__device__ float g_Yp[(size_t)NEXP * SEG * H];    // 512MB expert outputs
__device__ float g_Wt[(size_t)NEXP * H * H];      // 64MB  tf32-converted W
__device__ float g_Xt[(size_t)MAXT * H];          // 32MB  tf32-converted tokens

// ---------------- helpers ----------------
__device__ __forceinline__ unsigned f2tf(float f) {
    unsigned u;
    asm("cvt.rna.tf32.f32 %0, %1;" : "=r"(u) : "f"(f));
    return u;
}
__device__ __forceinline__ uint32_t s2u(const void* p) {
    uint32_t a;
    asm("{ .reg .u64 t; cvta.to.shared.u64 t, %1; cvt.u32.u64 %0, t; }"
        : "=r"(a) : "l"(p));
    return a;
}
__device__ __forceinline__ void cpa16(uint32_t dst, const void* src) {
    asm volatile("cp.async.cg.shared.global [%0], [%1], 16;" :: "r"(dst), "l"(src));
}
__device__ __forceinline__ void cpa_commit() {
    asm volatile("cp.async.commit_group;" ::: "memory");
}
__device__ __forceinline__ void cpa_wait2() {
    asm volatile("cp.async.wait_group 2;" ::: "memory");
}
__device__ __forceinline__ void mma8(float* c, const unsigned* a, const unsigned* b) {
    asm volatile(
        "mma.sync.aligned.m16n8k8.row.col.f32.tf32.tf32.f32 "
        "{%0,%1,%2,%3}, {%4,%5,%6,%7}, {%8,%9}, {%0,%1,%2,%3};"
        : "+f"(c[0]), "+f"(c[1]), "+f"(c[2]), "+f"(c[3])
        : "r"(a[0]), "r"(a[1]), "r"(a[2]), "r"(a[3]), "r"(b[0]), "r"(b[1]));
}

// ---------------- reset: zero per-expert cursors ----------------
__global__ void reset_kernel() {
    int i = threadIdx.x;
    if (i < NEXP) g_cursor[i] = 0;
}

// ---------------- cvt W -> tf32 bit patterns ----------------
__global__ void cvt_w_kernel(const float* __restrict__ src, int n4) {
    int i = blockIdx.x * blockDim.x + threadIdx.x;
    if (i >= n4) return;
    float4 v = ((const float4*)src)[i];
    uint4 u;
    u.x = f2tf(v.x); u.y = f2tf(v.y); u.z = f2tf(v.z); u.w = f2tf(v.w);
    ((uint4*)g_Wt)[i] = u;
}

// ---------------- router: warp per token; also converts X and scatters ----------------
__global__ void router_kernel(const float* __restrict__ x,
                              const float* __restrict__ rw,
                              const float* __restrict__ rb, int T) {
    extern __shared__ float s_rw[];

    int tid = threadIdx.x;
    for (int i = tid; i < NEXP * H; i += blockDim.x) s_rw[i] = rw[i];
    __syncthreads();

    int warp = tid >> 5, lane = tid & 31;
    int t = blockIdx.x * (blockDim.x >> 5) + warp;
    if (t >= T) return;

    const float* xr = x + (size_t)t * H;
    float* xo = g_Xt + (size_t)t * H;
    float acc[NEXP];
    #pragma unroll
    for (int e = 0; e < NEXP; ++e) acc[e] = 0.f;
    for (int i = lane; i < H; i += 32) {
        float xv = xr[i];
        xo[i] = __uint_as_float(f2tf(xv));        // fused tf32 conversion of X
        #pragma unroll
        for (int e = 0; e < NEXP; ++e) acc[e] += xv * s_rw[e * H + i];
    }
    #pragma unroll
    for (int e = 0; e < NEXP; ++e) {
        #pragma unroll
        for (int o = 16; o > 0; o >>= 1)
            acc[e] += __shfl_xor_sync(0xffffffffu, acc[e], o);
    }
    float logit = (lane < NEXP) ? (acc[lane] + rb[lane]) : -INFINITY;

    float mx = logit;
    #pragma unroll
    for (int o = 16; o > 0; o >>= 1)
        mx = fmaxf(mx, __shfl_xor_sync(0xffffffffu, mx, o));
    float p = (lane < NEXP) ? expf(logit - mx) : 0.f;
    float sum = p;
    #pragma unroll
    for (int o = 16; o > 0; o >>= 1)
        sum += __shfl_xor_sync(0xffffffffu, sum, o);
    float prob = p / sum;

    float cur = (lane < NEXP) ? prob : -1.f;
    float tv[TOPK]; int ti[TOPK];
    float s = 0.f;
    #pragma unroll
    for (int k = 0; k < TOPK; ++k) {
        float v = cur; int bi = lane;
        #pragma unroll
        for (int o = 16; o > 0; o >>= 1) {
            float ov = __shfl_xor_sync(0xffffffffu, v, o);
            int   oi = __shfl_xor_sync(0xffffffffu, bi, o);
            if (ov > v || (ov == v && oi < bi)) { v = ov; bi = oi; }
        }
        tv[k] = v; ti[k] = bi;
        s += v;
        if (lane == bi) cur = -1.f;
    }
    if (lane == 0) {
        float inv = 1.f / (s + EPS);
        float w[TOPK], sw = 0.f;
        #pragma unroll
        for (int k = 0; k < TOPK; ++k) { w[k] = tv[k] * inv; sw += w[k]; }
        g_sw[t] = sw;
        float isw = 1.f / sw;
        int b = t * TOPK;
        #pragma unroll
        for (int k = 0; k < TOPK; ++k) {
            int e = ti[k];
            int pos = atomicAdd(&g_cursor[e], 1);   // fixed-capacity segment scatter
            int row = e * SEG + pos;
            g_pair_token[row] = t;
            g_pairw[row] = w[k] * isw;
            g_pos[b + k] = row;
        }
    }
}

// ---------------- grouped GEMM: 128x256x32 tiles, cp.async 4-stage, tf32 mma ----------------
__global__ void __launch_bounds__(256, 1) gemm_kernel() {
    extern __shared__ char smem[];
    const int e  = blockIdx.z;
    const int cnt = g_cursor[e];
    const int mb = blockIdx.y * BM;       // local m within expert segment
    if (mb >= cnt) return;
    const int base = e * SEG + mb;        // global pair row base
    const int n0 = blockIdx.x * BN;

    const uint32_t sb = s2u(smem);
    const int tid = threadIdx.x;
    int*   s_tok = (int*)(smem + SM_TOK);
    float* s_w   = (float*)(smem + SM_W);

    if (tid < BM) {
        bool ok = (mb + tid) < cnt;
        s_tok[tid] = ok ? g_pair_token[base + tid] : 0;
        s_w[tid]   = ok ? g_pairw[base + tid] : 0.f;
    }
    __syncthreads();

    const float* wb = g_Wt + (size_t)e * H * H + n0;

    auto issue = [&](int s, int kt) {
        const int k0 = kt * BKK;
        uint32_t ab = sb + s * STAGE_BYTES;
        #pragma unroll
        for (int p = 0; p < 4; ++p) {
            int idx = tid + p * 256;
            int row = idx >> 3, i = idx & 7;
            cpa16(ab + (row * AST + i * 4) * 4,
                  g_Xt + (size_t)s_tok[row] * H + k0 + i * 4);
        }
        uint32_t bb = ab + A_BYTES;
        #pragma unroll
        for (int p = 0; p < 8; ++p) {
            int idx = tid + p * 256;
            int kr = idx >> 6, i = idx & 63;
            cpa16(bb + (kr * BSTRIDE + i * 4) * 4,
                  wb + (size_t)(k0 + kr) * H + i * 4);
        }
    };

    issue(0, 0); cpa_commit();
    issue(1, 1); cpa_commit();
    issue(2, 2); cpa_commit();

    float c[4][8][4];
    #pragma unroll
    for (int mi = 0; mi < 4; ++mi)
        #pragma unroll
        for (int ni = 0; ni < 8; ++ni)
            #pragma unroll
            for (int j = 0; j < 4; ++j) c[mi][ni][j] = 0.f;

    const int lane = tid & 31;
    const int grp = lane >> 2, tg = lane & 3;
    const int wid = tid >> 5;
    const int wm = (wid >> 2) * 64;
    const int wn = (wid & 3) * 64;

    for (int kt = 0; kt < NKT; ++kt) {
        cpa_wait2();
        __syncthreads();
        if (kt + 3 < NKT) issue((kt + 3) % STG, kt + 3);
        cpa_commit();

        const unsigned* As = (const unsigned*)(smem + (kt % STG) * STAGE_BYTES);
        const unsigned* Bs = As + BM * AST;

        #pragma unroll
        for (int kk = 0; kk < 4; ++kk) {
            const int k8 = kk * 8;
            unsigned a[4][4], b[8][2];
            #pragma unroll
            for (int mi = 0; mi < 4; ++mi) {
                int r = wm + mi * 16 + grp;
                a[mi][0] = As[r * AST + k8 + tg];
                a[mi][1] = As[(r + 8) * AST + k8 + tg];
                a[mi][2] = As[r * AST + k8 + tg + 4];
                a[mi][3] = As[(r + 8) * AST + k8 + tg + 4];
            }
            #pragma unroll
            for (int ni = 0; ni < 8; ++ni) {
                int cn = wn + ni * 8 + grp;
                b[ni][0] = Bs[(k8 + tg) * BSTRIDE + cn];
                b[ni][1] = Bs[(k8 + tg + 4) * BSTRIDE + cn];
            }
            #pragma unroll
            for (int mi = 0; mi < 4; ++mi)
                #pragma unroll
                for (int ni = 0; ni < 8; ++ni)
                    mma8(c[mi][ni], a[mi], b[ni]);
        }
    }

    // epilogue: scale by pair weight, store float2
    #pragma unroll
    for (int mi = 0; mi < 4; ++mi) {
        int rl0 = wm + mi * 16 + grp;
        int rl1 = rl0 + 8;
        float w0 = s_w[rl0], w1 = s_w[rl1];
        #pragma unroll
        for (int ni = 0; ni < 8; ++ni) {
            int col = n0 + wn + ni * 8 + tg * 2;
            if (mb + rl0 < cnt) {
                float2 v = make_float2(c[mi][ni][0] * w0, c[mi][ni][1] * w0);
                *(float2*)&g_Yp[(size_t)(base + rl0) * H + col] = v;
            }
            if (mb + rl1 < cnt) {
                float2 v = make_float2(c[mi][ni][2] * w1, c[mi][ni][3] * w1);
                *(float2*)&g_Yp[(size_t)(base + rl1) * H + col] = v;
            }
        }
    }
}

// ---------------- combine: out[t] = EPS*sw + sum_k Yp[pos_k] ----------------
__global__ void combine_kernel(float* __restrict__ out, int T) {
    int t = blockIdx.x;
    int c4 = threadIdx.x;
    int b = t * TOPK;
    int p0 = g_pos[b + 0], p1 = g_pos[b + 1], p2 = g_pos[b + 2];
    int p3 = g_pos[b + 3], p4 = g_pos[b + 4], p5 = g_pos[b + 5];
    float bias = EPS * g_sw[t];
    int col = c4 * 4;

    float4 acc = make_float4(bias, bias, bias, bias);
    float4 y;
    y = *(const float4*)&g_Yp[(size_t)p0 * H + col]; acc.x += y.x; acc.y += y.y; acc.z += y.z; acc.w += y.w;
    y = *(const float4*)&g_Yp[(size_t)p1 * H + col]; acc.x += y.x; acc.y += y.y; acc.z += y.z; acc.w += y.w;
    y = *(const float4*)&g_Yp[(size_t)p2 * H + col]; acc.x += y.x; acc.y += y.y; acc.z += y.z; acc.w += y.w;
    y = *(const float4*)&g_Yp[(size_t)p3 * H + col]; acc.x += y.x; acc.y += y.y; acc.z += y.z; acc.w += y.w;
    y = *(const float4*)&g_Yp[(size_t)p4 * H + col]; acc.x += y.x; acc.y += y.y; acc.z += y.z; acc.w += y.w;
    y = *(const float4*)&g_Yp[(size_t)p5 * H + col]; acc.x += y.x; acc.y += y.y; acc.z += y.z; acc.w += y.w;

    *(float4*)&out[(size_t)t * H + col] = acc;
}

// ---------------- launch ----------------
extern "C" void kernel_launch(void* const* d_in, const int* in_sizes, int n_in,
                              void* d_out, int out_size) {
    const float* tokens = (const float*)d_in[0];
    const float* rw     = (const float*)d_in[1];
    const float* rb     = (const float*)d_in[2];
    const float* ew     = (const float*)d_in[3];
    float* out = (float*)d_out;

    int T = in_sizes[0] / H;   // 8192

    reset_kernel<<<1, 32>>>();                                      // idx 0

    cvt_w_kernel<<<(NEXP * H * H / 4 + 255) / 256, 256>>>(ew, NEXP * H * H / 4);  // idx 1

    cudaFuncSetAttribute(router_kernel,
                         cudaFuncAttributeMaxDynamicSharedMemorySize, NEXP * H * 4);
    int warps_per_blk = 8;
    int rblocks = (T + warps_per_blk - 1) / warps_per_blk;
    router_kernel<<<rblocks, warps_per_blk * 32, NEXP * H * 4>>>(tokens, rw, rb, T);  // idx 2

    cudaFuncSetAttribute(gemm_kernel,
                         cudaFuncAttributeMaxDynamicSharedMemorySize, SM_TOTAL);
    dim3 ggrid(H / BN, SEG / BM, NEXP);   // (4, 64, 16); empty tiles exit fast
    gemm_kernel<<<ggrid, 256, SM_TOTAL>>>();                        // idx 3  <- profiled

    combine_kernel<<<T, 256>>>(out, T);                             // idx 4
}